// round 15
// baseline (speedup 1.0000x reference)
#include <cuda_runtime.h>
#include <cstdint>

#define NB      16384
#define DTC     0.1f
#define FPB     32
#define THREADS 128
#define RSTEP   20               // step slots per row (one 20-step segment)
#define FS      324              // filter stride (words): %4==0, FS/4=81 odd ->
                                 // minimal-wavefront LDS/STS.128 phases
#define SMEM_WORDS (32 * FS)     // 10368
#define SMEM_BYTES (SMEM_WORDS * 4)   // 41472 B -> 4 blocks/SM

struct St  { float x0,x1,x2,x3,p00,p01,p02,p03,p11,p12,p13,p22,p23,p33; };
struct Cst { float q00,q01,q02,q03,q11,q12,q13,q22,q23,q33,r00,r01,r11; };

// one exact-collapsed UKF step (affine motion => linear KF);
// Pn via K*A_c^T (== K S K^T since K = A_c S^{-1}); outputs into buf[.][j]
__device__ __forceinline__ void ukf_step(
    St& s, const Cst& c, float z0, float z1, float ux, float uy,
    float (&buf)[16][4], int j)
{
    const float xp0 = s.x0 + DTC * s.x2 + 0.5f * DTC * DTC * ux;
    const float xp1 = s.x1 + DTC * s.x3 + 0.5f * DTC * DTC * uy;
    const float xp2 = s.x2 + DTC * ux;
    const float xp3 = s.x3 + DTC * uy;

    const float a02 = s.p02 + DTC * s.p22;
    const float a03 = s.p03 + DTC * s.p23;
    const float a12 = s.p12 + DTC * s.p23;
    const float a13 = s.p13 + DTC * s.p33;
    const float a00 = s.p00 + DTC * s.p02 + DTC * a02;
    const float a11 = s.p11 + DTC * s.p13 + DTC * a13;
    const float a01 = s.p01 + DTC * s.p03 + DTC * a12;

    const float s00 = a00 + c.r00;
    const float s01 = a01 + c.r01;
    const float s11 = a11 + c.r11;
    const float idet = __fdividef(1.0f, s00 * s11 - s01 * s01);
    const float i00 =  s11 * idet;
    const float i01 = -s01 * idet;
    const float i11 =  s00 * idet;

    const float K00 = a00 * i00 + a01 * i01, K01 = a00 * i01 + a01 * i11;
    const float K10 = a01 * i00 + a11 * i01, K11 = a01 * i01 + a11 * i11;
    const float K20 = a02 * i00 + a12 * i01, K21 = a02 * i01 + a12 * i11;
    const float K30 = a03 * i00 + a13 * i01, K31 = a03 * i01 + a13 * i11;

    const float in0 = z0 - xp0, in1 = z1 - xp1;
    const float xn0 = xp0 + K00 * in0 + K01 * in1;
    const float xn1 = xp1 + K10 * in0 + K11 * in1;
    const float xn2 = xp2 + K20 * in0 + K21 * in1;
    const float xn3 = xp3 + K30 * in0 + K31 * in1;

    s.p00 = (a00 + c.q00) - (K00 * a00 + K01 * a01);
    s.p01 = (a01 + c.q01) - (K00 * a01 + K01 * a11);
    s.p02 = (a02 + c.q02) - (K00 * a02 + K01 * a12);
    s.p03 = (a03 + c.q03) - (K00 * a03 + K01 * a13);
    s.p11 = (a11 + c.q11) - (K10 * a01 + K11 * a11);
    s.p12 = (a12 + c.q12) - (K10 * a02 + K11 * a12);
    s.p13 = (a13 + c.q13) - (K10 * a03 + K11 * a13);
    s.p22 = (s.p22 + c.q22) - (K20 * a02 + K21 * a12);
    s.p23 = (s.p23 + c.q23) - (K20 * a03 + K21 * a13);
    s.p33 = (s.p33 + c.q33) - (K30 * a03 + K31 * a13);
    s.x0 = xn0; s.x1 = xn1; s.x2 = xn2; s.x3 = xn3;

    buf[0][j]  = xp0;   buf[1][j]  = xp1;
    buf[2][j]  = xn0;   buf[3][j]  = xn1;
    buf[4][j]  = xn2;   buf[5][j]  = xn3;
    buf[6][j]  = s.p00; buf[7][j]  = s.p01;
    buf[8][j]  = s.p02; buf[9][j]  = s.p03;
    buf[10][j] = s.p11; buf[11][j] = s.p12;
    buf[12][j] = s.p13; buf[13][j] = s.p22;
    buf[14][j] = s.p23; buf[15][j] = s.p33;
}

__global__ __launch_bounds__(THREADS, 4) void ukf_kernel(
    const float* __restrict__ meas, const float* __restrict__ state0,
    const float* __restrict__ cov0, const float* __restrict__ ctrl,
    const float* __restrict__ Qm,   const float* __restrict__ Rm,
    float* __restrict__ preds, float* __restrict__ states, float* __restrict__ covs)
{
    extern __shared__ float sm[];
    const int tid = threadIdx.x;
    const int bid = blockIdx.x;
    const int b0  = bid * FPB;
    // co-resident blocks differ by ~148 -> cw steps by 1 per block-wave
    const int cw  = ((bid >> 2) + bid) & 3;
    const bool comp = (tid >> 5) == cw;
    const int lane = tid & 31;

    // flush mapping (all threads): thread -> (filter, quarter-phase)
    const int ff = tid >> 2, fh = tid & 3;
    const float* fsrc = sm + ff * FS;
    float* fpp = preds  + (size_t)(b0 + ff) * 200;
    float* fps = states + (size_t)(b0 + ff) * 400;
    float* fpc = covs   + (size_t)(b0 + ff) * 1600;

    St s;  Cst c;
    const float* mrow = nullptr;
    const float* crow = nullptr;
    float* stage_f = nullptr;
    float4 pz0, pz1, pc0, pc1;                 // one 4-step group ahead

    if (comp) {
        const int b = b0 + lane;
        float4 xv = *reinterpret_cast<const float4*>(state0 + (size_t)b * 4);
        s.x0 = xv.x; s.x1 = xv.y; s.x2 = xv.z; s.x3 = xv.w;
        const float4* pv = reinterpret_cast<const float4*>(cov0 + (size_t)b * 16);
        float4 r0 = pv[0], r1 = pv[1], r2 = pv[2], r3 = pv[3];
        s.p00 = r0.x; s.p01 = r0.y; s.p02 = r0.z; s.p03 = r0.w;
        s.p11 = r1.y; s.p12 = r1.z; s.p13 = r1.w;
        s.p22 = r2.z; s.p23 = r2.w; s.p33 = r3.w;

        c.q00 = Qm[0];  c.q01 = Qm[1];  c.q02 = Qm[2];  c.q03 = Qm[3];
        c.q11 = Qm[5];  c.q12 = Qm[6];  c.q13 = Qm[7];
        c.q22 = Qm[10]; c.q23 = Qm[11]; c.q33 = Qm[15];
        c.r00 = Rm[0];  c.r01 = Rm[1];  c.r11 = Rm[3];

        mrow = meas + (size_t)b * 200;
        crow = ctrl + (size_t)b * 200;
        stage_f = sm + lane * FS;

        pz0 = *reinterpret_cast<const float4*>(mrow);
        pz1 = *reinterpret_cast<const float4*>(mrow + 100);
        pc0 = *reinterpret_cast<const float4*>(crow);
        pc1 = *reinterpret_cast<const float4*>(crow + 4);
    }

    // ---- 5 segments x 20 steps (5*20 = 100, no tail) ----
    // Inner group loop is ROLLED (#pragma unroll 1): hot body = ONE 4-step
    // block (~6KB SASS) reused 25x, instead of 28KB of unique straight-line
    // text per segment. This is the I$-streaming experiment.
#pragma unroll 1
    for (int seg = 0; seg < 5; seg++) {
        if (comp) {
#pragma unroll 1
            for (int j = 0; j < 5; j++) {
                const int gi = seg * 5 + j;              // 4-step group 0..24
                float4 z0 = pz0, z1 = pz1, u0 = pc0, u1 = pc1;
                if (gi < 24) {                            // prefetch next group
                    const int o = 4 * (gi + 1);
                    pz0 = *reinterpret_cast<const float4*>(mrow + o);
                    pz1 = *reinterpret_cast<const float4*>(mrow + 100 + o);
                    pc0 = *reinterpret_cast<const float4*>(crow + 2 * o);
                    pc1 = *reinterpret_cast<const float4*>(crow + 2 * o + 4);
                }
                float buf[16][4];
                ukf_step(s, c, z0.x, z1.x, u0.x, u0.y, buf, 0);
                ukf_step(s, c, z0.y, z1.y, u0.z, u0.w, buf, 1);
                ukf_step(s, c, z0.z, z1.z, u1.x, u1.y, buf, 2);
                ukf_step(s, c, z0.w, z1.w, u1.z, u1.w, buf, 3);
#pragma unroll
                for (int r = 0; r < 16; r++)
                    *reinterpret_cast<float4*>(stage_f + r * RSTEP + 4 * j) =
                        make_float4(buf[r][0], buf[r][1], buf[r][2], buf[r][3]);
            }
        }
        __syncthreads();                       // segment staged

        // division-free dense flush of 20 steps (G=5 float4 groups/row)
        {
            constexpr int MAP[22] = {0,1,2,3,4,5,
                                     6,7,8,9, 7,10,11,12, 8,11,13,14, 9,12,14,15};
            const int sglob = seg * RSTEP;
#pragma unroll
            for (int R = 0; R < 22; R++) {
                const float* src = fsrc + MAP[R] * RSTEP;
                float* dst = (R < 2) ? fpp + R * 100
                           : (R < 6) ? fps + (R - 2) * 100
                                     : fpc + (R - 6) * 100;
#pragma unroll
                for (int kk = 0; kk < 2; kk++) {
                    const int g = fh + 4 * kk;
                    if (g < 5) {
                        float4 v = *reinterpret_cast<const float4*>(src + 4 * g);
                        *reinterpret_cast<float4*>(dst + sglob + 4 * g) = v;
                    }
                }
            }
        }
        __syncthreads();                       // staging reusable
    }
}

extern "C" void kernel_launch(void* const* d_in, const int* in_sizes, int n_in,
                              void* d_out, int out_size)
{
    const float* meas  = (const float*)d_in[0];
    const float* state = (const float*)d_in[1];
    const float* cov   = (const float*)d_in[2];
    const float* ctrl  = (const float*)d_in[3];
    const float* Q     = (const float*)d_in[4];
    const float* R     = (const float*)d_in[5];

    float* out    = (float*)d_out;
    float* preds  = out;                         // 16384*2*100
    float* states = preds  + (size_t)NB * 200;   // 16384*4*100
    float* covs   = states + (size_t)NB * 400;   // 16384*16*100

    static int smem_set = 0;
    if (!smem_set) {
        cudaFuncSetAttribute(ukf_kernel,
                             cudaFuncAttributeMaxDynamicSharedMemorySize, SMEM_BYTES);
        smem_set = 1;
    }

    ukf_kernel<<<NB / FPB, THREADS, SMEM_BYTES>>>(meas, state, cov, ctrl, Q, R,
                                                  preds, states, covs);
}

// round 16
// speedup vs baseline: 1.0640x; 1.0640x over previous
#include <cuda_runtime.h>
#include <cstdint>

#define NB      16384
#define DTC     0.1f
#define FPB     64               // filters per block
#define THREADS 192              // 3 roles x 64 threads (2 warps each)
#define RSTEP   16               // step slots per staged row (one segment)
#define FS      260              // filter stride (words): %4==0, FS/4=65 odd ->
                                 // conflict-free LDS/STS.128 phases
#define SMEM_WORDS (FPB * FS)    // 16640
#define SMEM_BYTES (SMEM_WORDS * 4)   // 66560 B -> 2-3 blocks/SM

struct St  { float x0,x1,x2,x3,p00,p01,p02,p03,p11,p12,p13,p22,p23,p33; };
struct Cst { float q00,q01,q02,q03,q11,q12,q13,q22,q23,q33,r00,r01,r11; };

// one exact-collapsed UKF step (affine motion => linear KF);
// Pn via K*A_c^T (== K S K^T since K = A_c S^{-1}); outputs into buf[.][j]
__device__ __forceinline__ void ukf_step(
    St& s, const Cst& c, float z0, float z1, float ux, float uy,
    float (&buf)[16][4], int j)
{
    const float xp0 = s.x0 + DTC * s.x2 + 0.5f * DTC * DTC * ux;
    const float xp1 = s.x1 + DTC * s.x3 + 0.5f * DTC * DTC * uy;
    const float xp2 = s.x2 + DTC * ux;
    const float xp3 = s.x3 + DTC * uy;

    const float a02 = s.p02 + DTC * s.p22;
    const float a03 = s.p03 + DTC * s.p23;
    const float a12 = s.p12 + DTC * s.p23;
    const float a13 = s.p13 + DTC * s.p33;
    const float a00 = s.p00 + DTC * s.p02 + DTC * a02;
    const float a11 = s.p11 + DTC * s.p13 + DTC * a13;
    const float a01 = s.p01 + DTC * s.p03 + DTC * a12;

    const float s00 = a00 + c.r00;
    const float s01 = a01 + c.r01;
    const float s11 = a11 + c.r11;
    const float idet = __fdividef(1.0f, s00 * s11 - s01 * s01);
    const float i00 =  s11 * idet;
    const float i01 = -s01 * idet;
    const float i11 =  s00 * idet;

    const float K00 = a00 * i00 + a01 * i01, K01 = a00 * i01 + a01 * i11;
    const float K10 = a01 * i00 + a11 * i01, K11 = a01 * i01 + a11 * i11;
    const float K20 = a02 * i00 + a12 * i01, K21 = a02 * i01 + a12 * i11;
    const float K30 = a03 * i00 + a13 * i01, K31 = a03 * i01 + a13 * i11;

    const float in0 = z0 - xp0, in1 = z1 - xp1;
    const float xn0 = xp0 + K00 * in0 + K01 * in1;
    const float xn1 = xp1 + K10 * in0 + K11 * in1;
    const float xn2 = xp2 + K20 * in0 + K21 * in1;
    const float xn3 = xp3 + K30 * in0 + K31 * in1;

    s.p00 = (a00 + c.q00) - (K00 * a00 + K01 * a01);
    s.p01 = (a01 + c.q01) - (K00 * a01 + K01 * a11);
    s.p02 = (a02 + c.q02) - (K00 * a02 + K01 * a12);
    s.p03 = (a03 + c.q03) - (K00 * a03 + K01 * a13);
    s.p11 = (a11 + c.q11) - (K10 * a01 + K11 * a11);
    s.p12 = (a12 + c.q12) - (K10 * a02 + K11 * a12);
    s.p13 = (a13 + c.q13) - (K10 * a03 + K11 * a13);
    s.p22 = (s.p22 + c.q22) - (K20 * a02 + K21 * a12);
    s.p23 = (s.p23 + c.q23) - (K20 * a03 + K21 * a13);
    s.p33 = (s.p33 + c.q33) - (K30 * a03 + K31 * a13);
    s.x0 = xn0; s.x1 = xn1; s.x2 = xn2; s.x3 = xn3;

    buf[0][j]  = xp0;   buf[1][j]  = xp1;
    buf[2][j]  = xn0;   buf[3][j]  = xn1;
    buf[4][j]  = xn2;   buf[5][j]  = xn3;
    buf[6][j]  = s.p00; buf[7][j]  = s.p01;
    buf[8][j]  = s.p02; buf[9][j]  = s.p03;
    buf[10][j] = s.p11; buf[11][j] = s.p12;
    buf[12][j] = s.p13; buf[13][j] = s.p22;
    buf[14][j] = s.p23; buf[15][j] = s.p33;
}

// flush one filter's 22 output rows for one 16-step segment, float4 group gs
__device__ __forceinline__ void flush_one(
    const float* __restrict__ sm, float* __restrict__ preds,
    float* __restrict__ states, float* __restrict__ covs,
    int b0, int f, int gs, int sglob)
{
    constexpr int MAP[22] = {0,1,2,3,4,5,
                             6,7,8,9, 7,10,11,12, 8,11,13,14, 9,12,14,15};
    const float* src_f = sm + f * FS;
    const int gb = b0 + f;
    float* pp = preds  + (size_t)gb * 200;
    float* ps = states + (size_t)gb * 400;
    float* pc = covs   + (size_t)gb * 1600;
#pragma unroll
    for (int R = 0; R < 22; R++) {
        float4 v = *reinterpret_cast<const float4*>(src_f + MAP[R] * RSTEP + 4 * gs);
        float* dst = (R < 2) ? pp + R * 100
                   : (R < 6) ? ps + (R - 2) * 100
                             : pc + (R - 6) * 100;
        *reinterpret_cast<float4*>(dst + sglob + 4 * gs) = v;
    }
}

__global__ __launch_bounds__(THREADS, 2) void ukf_kernel(
    const float* __restrict__ meas, const float* __restrict__ state0,
    const float* __restrict__ cov0, const float* __restrict__ ctrl,
    const float* __restrict__ Qm,   const float* __restrict__ Rm,
    float* __restrict__ preds, float* __restrict__ states, float* __restrict__ covs)
{
    extern __shared__ float sm[];
    const int tid  = threadIdx.x;
    const int bid  = blockIdx.x;
    const int b0   = bid * FPB;
    const int role = tid >> 6;            // 0,1,2 (2 warps each, warp-uniform)
    const int fl   = tid & 63;            // filter lane within block

    // flush mapping: thread -> (f0, gs); second f iteration covers 48..63
    const int f0 = tid >> 2;              // 0..47
    const int gs = tid & 3;               // float4 group within 16-step segment

    // per-role compute schedule
    const int myend   = (role == 0) ? 4 : 6;   // segments this role computes
    const int mystart = (role == 0) ? 0 : ((role == 1) ? 4 : 6);  // first staged seg

    // ---- per-filter state (all roles: same filter, redundant chains) ----
    St s;  Cst c;
    {
        const int b = b0 + fl;
        float4 xv = *reinterpret_cast<const float4*>(state0 + (size_t)b * 4);
        s.x0 = xv.x; s.x1 = xv.y; s.x2 = xv.z; s.x3 = xv.w;
        const float4* pv = reinterpret_cast<const float4*>(cov0 + (size_t)b * 16);
        float4 r0 = pv[0], r1 = pv[1], r2 = pv[2], r3 = pv[3];
        s.p00 = r0.x; s.p01 = r0.y; s.p02 = r0.z; s.p03 = r0.w;
        s.p11 = r1.y; s.p12 = r1.z; s.p13 = r1.w;
        s.p22 = r2.z; s.p23 = r2.w; s.p33 = r3.w;
    }
    c.q00 = Qm[0];  c.q01 = Qm[1];  c.q02 = Qm[2];  c.q03 = Qm[3];
    c.q11 = Qm[5];  c.q12 = Qm[6];  c.q13 = Qm[7];
    c.q22 = Qm[10]; c.q23 = Qm[11]; c.q33 = Qm[15];
    c.r00 = Rm[0];  c.r01 = Rm[1];  c.r11 = Rm[3];

    const float* mrow = meas + (size_t)(b0 + fl) * 200;
    const float* crow = ctrl + (size_t)(b0 + fl) * 200;
    float* stage_f = sm + fl * FS;

    // prefetch 4-step group 0
    float4 pz0 = *reinterpret_cast<const float4*>(mrow);
    float4 pz1 = *reinterpret_cast<const float4*>(mrow + 100);
    float4 pc0 = *reinterpret_cast<const float4*>(crow);
    float4 pc1 = *reinterpret_cast<const float4*>(crow + 4);

    // ---- 6 segments x 16 steps (steps 0..95) ----
#pragma unroll 1
    for (int seg = 0; seg < 6; seg++) {
        if (seg < myend) {
            const bool stg = (seg >= mystart);
#pragma unroll
            for (int j = 0; j < 4; j++) {
                const int gi = seg * 4 + j;              // 4-step group 0..23
                float4 z0 = pz0, z1 = pz1, u0 = pc0, u1 = pc1;
                {   // prefetch next group (gi+1 <= 24: steps 96..99 in-bounds)
                    const int o = 4 * (gi + 1);
                    pz0 = *reinterpret_cast<const float4*>(mrow + o);
                    pz1 = *reinterpret_cast<const float4*>(mrow + 100 + o);
                    pc0 = *reinterpret_cast<const float4*>(crow + 2 * o);
                    pc1 = *reinterpret_cast<const float4*>(crow + 2 * o + 4);
                }
                float buf[16][4];
                ukf_step(s, c, z0.x, z1.x, u0.x, u0.y, buf, 0);
                ukf_step(s, c, z0.y, z1.y, u0.z, u0.w, buf, 1);
                ukf_step(s, c, z0.z, z1.z, u1.x, u1.y, buf, 2);
                ukf_step(s, c, z0.w, z1.w, u1.z, u1.w, buf, 3);
                if (stg) {
#pragma unroll
                    for (int r = 0; r < 16; r++)
                        *reinterpret_cast<float4*>(stage_f + r * RSTEP + 4 * j) =
                            make_float4(buf[r][0], buf[r][1], buf[r][2], buf[r][3]);
                }
            }
        }
        __syncthreads();                 // segment staged
        {
            const int sglob = seg * 16;
            flush_one(sm, preds, states, covs, b0, f0, gs, sglob);
            if (f0 < 16)
                flush_one(sm, preds, states, covs, b0, f0 + 48, gs, sglob);
        }
        __syncthreads();                 // staging reusable
    }

    // ---- tail: steps 96..99 (role2 computes + stages into slots 0..3) ----
    if (role == 2) {
        float buf[16][4];
        ukf_step(s, c, pz0.x, pz1.x, pc0.x, pc0.y, buf, 0);
        ukf_step(s, c, pz0.y, pz1.y, pc0.z, pc0.w, buf, 1);
        ukf_step(s, c, pz0.z, pz1.z, pc1.x, pc1.y, buf, 2);
        ukf_step(s, c, pz0.w, pz1.w, pc1.z, pc1.w, buf, 3);
#pragma unroll
        for (int r = 0; r < 16; r++)
            *reinterpret_cast<float4*>(stage_f + r * RSTEP) =
                make_float4(buf[r][0], buf[r][1], buf[r][2], buf[r][3]);
    }
    __syncthreads();
    if (gs == 0) {                        // one float4 per row (steps 96..99)
        flush_one(sm, preds, states, covs, b0, f0, 0, 96);
        if (f0 < 16)
            flush_one(sm, preds, states, covs, b0, f0 + 48, 0, 96);
    }
}

extern "C" void kernel_launch(void* const* d_in, const int* in_sizes, int n_in,
                              void* d_out, int out_size)
{
    const float* meas  = (const float*)d_in[0];
    const float* state = (const float*)d_in[1];
    const float* cov   = (const float*)d_in[2];
    const float* ctrl  = (const float*)d_in[3];
    const float* Q     = (const float*)d_in[4];
    const float* R     = (const float*)d_in[5];

    float* out    = (float*)d_out;
    float* preds  = out;                         // 16384*2*100
    float* states = preds  + (size_t)NB * 200;   // 16384*4*100
    float* covs   = states + (size_t)NB * 400;   // 16384*16*100

    static int smem_set = 0;
    if (!smem_set) {
        cudaFuncSetAttribute(ukf_kernel,
                             cudaFuncAttributeMaxDynamicSharedMemorySize, SMEM_BYTES);
        smem_set = 1;
    }

    ukf_kernel<<<NB / FPB, THREADS, SMEM_BYTES>>>(meas, state, cov, ctrl, Q, R,
                                                  preds, states, covs);
}